// round 16
// baseline (speedup 1.0000x reference)
#include <cuda_runtime.h>
#include <cuda_bf16.h>
#include <cuda_fp16.h>
#include <math.h>

// Problem constants
#define Bv 4
#define Lv 2048
#define Dv 1024
#define Hv 16
#define HDv 64
#define Mv (Bv * Lv)          // 8192 rows
#define EPSv 1e-5f

// ---------------- scratch (device globals; no allocs allowed) ----------------
__device__ __nv_bfloat16 g_xh[Mv * Dv];             // x in bf16
__device__ __nv_bfloat16 g_Wh[4 * Dv * Dv];         // Wq,Wk,Wv,Wo in bf16
__device__ __nv_bfloat16 g_Qh[Bv * Hv * Lv * HDv];  // [B,H,L,HD], pre-scaled
__device__ __nv_bfloat16 g_Kh[Bv * Hv * Lv * HDv];
__device__ __half        g_Vh[Bv * Hv * Lv * HDv];  // V in fp16 (PV mma is f16)
__device__ __nv_bfloat16 g_Oh[Mv * Dv];             // attention out, bf16 [B,L,D]
__device__ float g_Y[Mv * Dv];                      // pre-LN residual sum

// ---------------- helpers ----------------
__device__ __forceinline__ float ex2(float x) {
    float y;
    asm("ex2.approx.ftz.f32 %0, %1;" : "=f"(y) : "f"(x));
    return y;
}

__device__ __forceinline__ unsigned smem_u32(const void* p) {
    return (unsigned)__cvta_generic_to_shared(p);
}

__device__ __forceinline__ void cp_async16(unsigned dst, const void* src) {
    asm volatile("cp.async.cg.shared.global [%0], [%1], 16;" :: "r"(dst), "l"(src));
}
__device__ __forceinline__ void cp_commit() {
    asm volatile("cp.async.commit_group;");
}
template<int N> __device__ __forceinline__ void cp_wait() {
    asm volatile("cp.async.wait_group %0;" :: "n"(N));
}

__device__ __forceinline__ void mma_bf16(float* c, unsigned a0, unsigned a1, unsigned a2, unsigned a3,
                                         unsigned b0, unsigned b1) {
    asm volatile(
        "mma.sync.aligned.m16n8k16.row.col.f32.bf16.bf16.f32 "
        "{%0,%1,%2,%3}, {%4,%5,%6,%7}, {%8,%9}, {%0,%1,%2,%3};"
        : "+f"(c[0]), "+f"(c[1]), "+f"(c[2]), "+f"(c[3])
        : "r"(a0), "r"(a1), "r"(a2), "r"(a3), "r"(b0), "r"(b1));
}

__device__ __forceinline__ void mma_f16(float* c, unsigned a0, unsigned a1, unsigned a2, unsigned a3,
                                        unsigned b0, unsigned b1) {
    asm volatile(
        "mma.sync.aligned.m16n8k16.row.col.f32.f16.f16.f32 "
        "{%0,%1,%2,%3}, {%4,%5,%6,%7}, {%8,%9}, {%0,%1,%2,%3};"
        : "+f"(c[0]), "+f"(c[1]), "+f"(c[2]), "+f"(c[3])
        : "r"(a0), "r"(a1), "r"(a2), "r"(a3), "r"(b0), "r"(b1));
}

__device__ __forceinline__ void ldsm4(unsigned& r0, unsigned& r1, unsigned& r2, unsigned& r3, unsigned addr) {
    asm volatile("ldmatrix.sync.aligned.m8n8.x4.shared.b16 {%0,%1,%2,%3}, [%4];"
                 : "=r"(r0), "=r"(r1), "=r"(r2), "=r"(r3) : "r"(addr));
}
__device__ __forceinline__ void ldsm4t(unsigned& r0, unsigned& r1, unsigned& r2, unsigned& r3, unsigned addr) {
    asm volatile("ldmatrix.sync.aligned.m8n8.x4.trans.shared.b16 {%0,%1,%2,%3}, [%4];"
                 : "=r"(r0), "=r"(r1), "=r"(r2), "=r"(r3) : "r"(addr));
}

// pack exp2(a - m), exp2(b - m) into one f16x2 via one MUFU (lo = a-m, hi = b-m)
__device__ __forceinline__ unsigned exp2_f16x2(float a, float b, float m) {
    unsigned r;
    asm("cvt.rn.f16x2.f32 %0, %1, %2;" : "=r"(r) : "f"(b - m), "f"(a - m));
    asm("ex2.approx.f16x2 %0, %0;" : "+r"(r));
    return r;
}

// ---------------- pre-pass: fp32 -> bf16 ----------------
__global__ __launch_bounds__(256)
void bf16_cvt_kernel(const float* __restrict__ s0, const float* __restrict__ s1,
                     const float* __restrict__ s2, const float* __restrict__ s3,
                     __nv_bfloat16* __restrict__ dst, int n4)
{
    const int i = blockIdx.x * 256 + threadIdx.x;
    const float* src = (blockIdx.y == 0) ? s0 : ((blockIdx.y == 1) ? s1 : ((blockIdx.y == 2) ? s2 : s3));
    if (i < n4 && src) {
        float4 v = ((const float4*)src)[i];
        __nv_bfloat162 lo = __float22bfloat162_rn(make_float2(v.x, v.y));
        __nv_bfloat162 hi = __float22bfloat162_rn(make_float2(v.z, v.w));
        uint2 pack;
        pack.x = *(unsigned*)&lo;
        pack.y = *(unsigned*)&hi;
        ((uint2*)(dst + (size_t)blockIdx.y * Dv * Dv))[i] = pack;
    }
}

__global__ __launch_bounds__(256)
void bf16_cvt_x_kernel(const float* __restrict__ src, __nv_bfloat16* __restrict__ dst, int n4)
{
    const int i = blockIdx.x * 256 + threadIdx.x;
    if (i < n4) {
        float4 v = ((const float4*)src)[i];
        __nv_bfloat162 lo = __float22bfloat162_rn(make_float2(v.x, v.y));
        __nv_bfloat162 hi = __float22bfloat162_rn(make_float2(v.z, v.w));
        uint2 pack;
        pack.x = *(unsigned*)&lo;
        pack.y = *(unsigned*)&hi;
        ((uint2*)dst)[i] = pack;
    }
}

// ---------------- bf16 tensor-core GEMM, 4-stage cp.async pipeline ----------------
// mode 0: fused QKV. grid (24, 64). A = g_xh, W = g_Wh[wsel], out Q/K bf16, V fp16.
// mode 1: Wo.        grid (8, 64).  A = g_Oh, W = g_Wh[3], out g_Y fp32 (+residual x).
#define GSTAGES 4
#define ASTR 40
#define BSTR 136
#define A_STAGE (128 * ASTR)
#define B_STAGE (32 * BSTR)
#define GEMM_SMEM (GSTAGES * (A_STAGE + B_STAGE) * 2)   // 75776 B

__global__ __launch_bounds__(256, 2)
void gemm_tc_kernel(int mode,
                    const float* __restrict__ bq, const float* __restrict__ bk,
                    const float* __restrict__ bv, const float* __restrict__ bo,
                    const float* __restrict__ xres)
{
    extern __shared__ __nv_bfloat16 gsm[];
    __nv_bfloat16* sA = gsm;
    __nv_bfloat16* sB = gsm + GSTAGES * A_STAGE;

    const __nv_bfloat16* A;
    const __nv_bfloat16* W;
    const float* bias;
    int wsel, bcol;
    if (mode == 0) {
        wsel = blockIdx.x >> 3;
        bcol = blockIdx.x & 7;
        A = g_xh;
        W = g_Wh + (size_t)wsel * Dv * Dv;
        bias = (wsel == 0) ? bq : ((wsel == 1) ? bk : bv);
    } else {
        wsel = 3;
        bcol = blockIdx.x;
        A = g_Oh;
        W = g_Wh + (size_t)3 * Dv * Dv;
        bias = bo;
    }

    const int tid  = threadIdx.x;
    const int brow = blockIdx.y;
    const int wid  = tid >> 5;
    const int lane = tid & 31;
    const int wm   = wid & 1;
    const int wn   = wid >> 1;
    const int row4 = lane >> 2;
    const int col  = lane & 3;

    const int ac0_row = tid >> 2,          ac_kc = (tid & 3) * 8;
    const int ac1_row = (tid + 256) >> 2;
    const int bc0_row = tid >> 4,          bc_nc = (tid & 15) * 8;
    const int bc1_row = (tid + 256) >> 4;

    const __nv_bfloat16* Agb = A + (size_t)(brow * 128) * Dv;
    const __nv_bfloat16* Wgb = W + bcol * 128;

    float acc[4][4][4];
#pragma unroll
    for (int i = 0; i < 4; i++)
#pragma unroll
        for (int j = 0; j < 4; j++)
#pragma unroll
            for (int r = 0; r < 4; r++) acc[i][j][r] = 0.f;

    auto copy_stage = [&](int s, int k0) {
        __nv_bfloat16* as = sA + s * A_STAGE;
        __nv_bfloat16* bs = sB + s * B_STAGE;
        cp_async16(smem_u32(as + ac0_row * ASTR + ac_kc),
                   Agb + (size_t)ac0_row * Dv + k0 + ac_kc);
        cp_async16(smem_u32(as + ac1_row * ASTR + ac_kc),
                   Agb + (size_t)ac1_row * Dv + k0 + ac_kc);
        cp_async16(smem_u32(bs + bc0_row * BSTR + bc_nc),
                   Wgb + (size_t)(k0 + bc0_row) * Dv + bc_nc);
        cp_async16(smem_u32(bs + bc1_row * BSTR + bc_nc),
                   Wgb + (size_t)(k0 + bc1_row) * Dv + bc_nc);
    };

    const int NK = Dv / 32;
#pragma unroll
    for (int s = 0; s < GSTAGES - 1; s++) {
        copy_stage(s, s * 32);
        cp_commit();
    }

    int stg_c = 0;
    int stg_l = GSTAGES - 1;
    for (int kt = 0; kt < NK; kt++) {
        cp_wait<GSTAGES - 2>();
        __syncthreads();

        const int nxt = kt + GSTAGES - 1;
        if (nxt < NK) copy_stage(stg_l, nxt * 32);
        cp_commit();

        const __nv_bfloat16* as = sA + stg_c * A_STAGE;
        const __nv_bfloat16* bs = sB + stg_c * B_STAGE;

        const unsigned aB = smem_u32(as) +
            (unsigned)((wm * 64 + (lane & 15)) * ASTR + ((lane >> 4) << 3)) * 2;
        const unsigned bB = smem_u32(bs) +
            (unsigned)(((((lane >> 3) & 1) << 3) + (lane & 7)) * BSTR +
                       wn * 32 + ((lane >> 4) << 3)) * 2;

#pragma unroll
        for (int kc = 0; kc < 2; kc++) {
            unsigned af[4][4];
#pragma unroll
            for (int i = 0; i < 4; i++)
                ldsm4(af[i][0], af[i][1], af[i][2], af[i][3],
                      aB + (unsigned)(i * 16 * ASTR + kc * 16) * 2);
#pragma unroll
            for (int jp = 0; jp < 2; jp++) {
                unsigned b0, b1, b2, b3;
                ldsm4t(b0, b1, b2, b3, bB + (unsigned)(kc * 16 * BSTR + jp * 16) * 2);
#pragma unroll
                for (int i = 0; i < 4; i++) {
                    mma_bf16(acc[i][2 * jp],     af[i][0], af[i][1], af[i][2], af[i][3], b0, b1);
                    mma_bf16(acc[i][2 * jp + 1], af[i][0], af[i][1], af[i][2], af[i][3], b2, b3);
                }
            }
        }
        __syncthreads();
        stg_c = (stg_c == GSTAGES - 1) ? 0 : stg_c + 1;
        stg_l = (stg_l == GSTAGES - 1) ? 0 : stg_l + 1;
    }

    // epilogue
    const float qsc = 0.125f * 1.4426950408889634f;
#pragma unroll
    for (int i = 0; i < 4; i++) {
#pragma unroll
        for (int j = 0; j < 4; j++) {
            const int m_lo = brow * 128 + wm * 64 + i * 16 + row4;
            const int n0   = bcol * 128 + wn * 32 + j * 8 + col * 2;
#pragma unroll
            for (int half = 0; half < 2; half++) {
                const int m = m_lo + half * 8;
                float v0 = acc[i][j][half * 2 + 0] + bias[n0];
                float v1 = acc[i][j][half * 2 + 1] + bias[n0 + 1];
                if (mode == 1) {
                    v0 += xres[(size_t)m * Dv + n0];
                    v1 += xres[(size_t)m * Dv + n0 + 1];
                    *(float2*)&g_Y[(size_t)m * Dv + n0] = make_float2(v0, v1);
                } else {
                    const int b = m >> 11, l = m & 2047;
                    const int h = n0 >> 6, hd = n0 & 63;
                    const size_t idx = ((((size_t)b * Hv + h) * Lv) + l) * HDv + hd;
                    if (wsel == 2) {
                        *(__half2*)&g_Vh[idx] = __float22half2_rn(make_float2(v0, v1));
                    } else {
                        if (wsel == 0) { v0 *= qsc; v1 *= qsc; }
                        __nv_bfloat16* dst = (wsel == 0) ? g_Qh : g_Kh;
                        *(__nv_bfloat162*)&dst[idx] = __float22bfloat162_rn(make_float2(v0, v1));
                    }
                }
            }
        }
    }
}

// ---------------- flash attention: FA2 register-P, Br=64, 4 CTAs/SM ----------------
// 128 thr / 4 warps, Br=64, Bc=64, warp M=16. Q hoisted to registers.
// P lives in registers (S C-frags -> exp -> f16x2 A-frags for PV).
// smem: 3 stages x (K[64][72] + V[64][72]). One __syncthreads per tile.
#define FQS 72
#define STG_EL (128 * FQS)
#define FLASH_SMEM (3 * STG_EL * 2)   // 55296 B
#define ONES_F16X2 0x3C003C00u

__global__ __launch_bounds__(128, 4)
void flash_tc_kernel()
{
    extern __shared__ __nv_bfloat16 fsm[];
    const unsigned sbase = smem_u32(fsm);

    const int tid  = threadIdx.x;
    const int bh   = blockIdx.y;
    const int qb   = blockIdx.x;         // q tile of 64
    const int wid  = tid >> 5;           // 0..3
    const int lane = tid & 31;
    const int qw   = wid * 16;
    const int g    = lane >> 2;
    const int t    = lane & 3;

    const __nv_bfloat16* Qg = g_Qh + ((size_t)bh * Lv + qb * 64) * HDv;
    const __nv_bfloat16* Kg = g_Kh + (size_t)bh * Lv * HDv;
    const __half*        Vg = g_Vh + (size_t)bh * Lv * HDv;

    // KV loader: 128 threads, each loads one full 128B row (K rows 0-63, V rows 64-127)
    auto load_kv = [&](int kb, int stg) {
        const void* src = (tid < 64)
            ? (const void*)(Kg + (size_t)(kb * 64 + tid) * HDv)
            : (const void*)(Vg + (size_t)(kb * 64 + tid - 64) * HDv);
        const unsigned dst = sbase + (unsigned)(stg * STG_EL + tid * FQS) * 2;
#pragma unroll
        for (int u = 0; u < 8; u++) cp_async16(dst + u * 16, (const char*)src + u * 16);
    };

    // prologue: Q (64 rows) into stage-2 region; KV tiles 0,1 into stages 0,1
    {
        const int qrow  = tid >> 1;          // 0..63
        const int qcolb = (tid & 1) * 64;
        const __nv_bfloat16* qs = Qg + (size_t)qrow * HDv + qcolb / 2;
        const unsigned qd = sbase + (unsigned)(2 * STG_EL + qrow * FQS) * 2 + qcolb;
#pragma unroll
        for (int u = 0; u < 4; u++) cp_async16(qd + u * 16, qs + u * 8);
        load_kv(0, 0);
        cp_commit();          // group = {Q, kv0}
        load_kv(1, 1);
        cp_commit();          // group = {kv1}
    }
    cp_wait<1>();             // Q + kv0 resident
    __syncthreads();

    // hoist Q fragments from stage-2 region
    const int a_row = lane & 15;
    const int a_k8  = (lane >> 4) << 3;
    unsigned qf[4][4];
    {
        const unsigned qA = sbase + (unsigned)(2 * STG_EL + (qw + a_row) * FQS + a_k8) * 2;
#pragma unroll
        for (int kc = 0; kc < 4; kc++)
            ldsm4(qf[kc][0], qf[kc][1], qf[kc][2], qf[kc][3], qA + kc * 32);
    }

    const int b_row = ((lane >> 4) << 3) + (lane & 7);
    const int b_k8  = ((lane >> 3) & 1) << 3;
    const int v_row = (((lane >> 3) & 1) << 3) + (lane & 7);
    const int v_col = (lane >> 4) << 3;

    float m0 = -1e30f, m1 = -1e30f, l0 = 0.f, l1 = 0.f;
    float o[8][4];
#pragma unroll
    for (int j = 0; j < 8; j++)
#pragma unroll
        for (int r = 0; r < 4; r++) o[j][r] = 0.f;

    const int NT = Lv / 64;   // 32
    int stg = 0;
    int stg_l = 2;
    for (int kb = 0; kb < NT; kb++) {
        cp_wait<1>();
        __syncthreads();      // tile kb resident; stage stg_l fully read by all warps

        if (kb + 2 < NT) load_kv(kb + 2, stg_l);
        cp_commit();

        const unsigned kB = sbase + (unsigned)(stg * STG_EL + b_row * FQS + b_k8) * 2;
        const unsigned vB = sbase + (unsigned)(stg * STG_EL + 64 * FQS + v_row * FQS + v_col) * 2;

        // ---- S = Q K^T (bf16) ----
        float s[8][4];
#pragma unroll
        for (int j = 0; j < 8; j++)
#pragma unroll
            for (int r = 0; r < 4; r++) s[j][r] = 0.f;

#pragma unroll
        for (int kc = 0; kc < 4; kc++) {
#pragma unroll
            for (int jp = 0; jp < 4; jp++) {
                unsigned b0, b1, b2, b3;
                ldsm4(b0, b1, b2, b3, kB + (unsigned)(jp * 16 * FQS + kc * 16) * 2);
                mma_bf16(s[2 * jp],     qf[kc][0], qf[kc][1], qf[kc][2], qf[kc][3], b0, b1);
                mma_bf16(s[2 * jp + 1], qf[kc][0], qf[kc][1], qf[kc][2], qf[kc][3], b2, b3);
            }
        }

        // ---- online softmax (log2 domain), P built in registers ----
        float rmax0 = -1e30f, rmax1 = -1e30f;
#pragma unroll
        for (int j = 0; j < 8; j++) {
            rmax0 = fmaxf(rmax0, fmaxf(s[j][0], s[j][1]));
            rmax1 = fmaxf(rmax1, fmaxf(s[j][2], s[j][3]));
        }
#pragma unroll
        for (int off = 1; off <= 2; off <<= 1) {
            rmax0 = fmaxf(rmax0, __shfl_xor_sync(0xffffffffu, rmax0, off));
            rmax1 = fmaxf(rmax1, __shfl_xor_sync(0xffffffffu, rmax1, off));
        }
        const float mn0 = fmaxf(m0, rmax0);
        const float mn1 = fmaxf(m1, rmax1);
        const float cr0 = ex2(m0 - mn0);
        const float cr1 = ex2(m1 - mn1);
        m0 = mn0; m1 = mn1;

#pragma unroll
        for (int j = 0; j < 8; j++) {
            o[j][0] *= cr0; o[j][1] *= cr0;
            o[j][2] *= cr1; o[j][3] *= cr1;
        }

        // ---- O += P V (f16), P as register A-fragments; row-sum via ones-mma ----
        float lsum[4] = {0.f, 0.f, 0.f, 0.f};
#pragma unroll
        for (int kc = 0; kc < 4; kc++) {
            const unsigned pa0 = exp2_f16x2(s[2 * kc][0],     s[2 * kc][1],     mn0);
            const unsigned pa1 = exp2_f16x2(s[2 * kc][2],     s[2 * kc][3],     mn1);
            const unsigned pa2 = exp2_f16x2(s[2 * kc + 1][0], s[2 * kc + 1][1], mn0);
            const unsigned pa3 = exp2_f16x2(s[2 * kc + 1][2], s[2 * kc + 1][3], mn1);
            mma_f16(lsum, pa0, pa1, pa2, pa3, ONES_F16X2, ONES_F16X2);
#pragma unroll
            for (int jp = 0; jp < 4; jp++) {
                unsigned b0, b1, b2, b3;
                ldsm4t(b0, b1, b2, b3, vB + (unsigned)(kc * 16 * FQS + jp * 16) * 2);
                mma_f16(o[2 * jp],     pa0, pa1, pa2, pa3, b0, b1);
                mma_f16(o[2 * jp + 1], pa0, pa1, pa2, pa3, b2, b3);
            }
        }
        l0 = l0 * cr0 + lsum[0];
        l1 = l1 * cr1 + lsum[2];

        stg   = (stg   == 2) ? 0 : stg + 1;
        stg_l = (stg_l == 2) ? 0 : stg_l + 1;
    }

    // ---- write O to g_Oh [B,L,D] in bf16 ----
    const int b = bh >> 4, h = bh & 15;
    const float inv0 = 1.f / l0;
    const float inv1 = 1.f / l1;
    const int q0 = qb * 64 + qw + g;
    const int q1 = q0 + 8;
#pragma unroll
    for (int j = 0; j < 8; j++) {
        const int colD = h * HDv + j * 8 + 2 * t;
        *(__nv_bfloat162*)&g_Oh[((size_t)b * Lv + q0) * Dv + colD] =
            __float22bfloat162_rn(make_float2(o[j][0] * inv0, o[j][1] * inv0));
        *(__nv_bfloat162*)&g_Oh[((size_t)b * Lv + q1) * Dv + colD] =
            __float22bfloat162_rn(make_float2(o[j][2] * inv1, o[j][3] * inv1));
    }
}

// ---------------- LayerNorm: one WARP per row ----------------
__global__ __launch_bounds__(256)
void layernorm_kernel(const float* __restrict__ gamma,
                      const float* __restrict__ beta,
                      float* __restrict__ out)
{
    const int row  = blockIdx.x * 8 + (threadIdx.x >> 5);
    const int lane = threadIdx.x & 31;
    const float4* y4 = (const float4*)(g_Y + (size_t)row * Dv);

    float4 v[8];
    float sum = 0.f;
#pragma unroll
    for (int i = 0; i < 8; i++) {
        v[i] = y4[lane + i * 32];
        sum += v[i].x + v[i].y + v[i].z + v[i].w;
    }
#pragma unroll
    for (int off = 16; off > 0; off >>= 1)
        sum += __shfl_xor_sync(0xffffffffu, sum, off);
    const float mu = sum * (1.f / Dv);

    float d2 = 0.f;
#pragma unroll
    for (int i = 0; i < 8; i++) {
        float a = v[i].x - mu, b = v[i].y - mu, c = v[i].z - mu, d = v[i].w - mu;
        d2 += a * a + b * b + c * c + d * d;
    }
#pragma unroll
    for (int off = 16; off > 0; off >>= 1)
        d2 += __shfl_xor_sync(0xffffffffu, d2, off);
    const float rs = rsqrtf(d2 * (1.f / Dv) + EPSv);

    float4* o4 = (float4*)(out + (size_t)row * Dv);
    const float4* g4 = (const float4*)gamma;
    const float4* b4 = (const float4*)beta;
#pragma unroll
    for (int i = 0; i < 8; i++) {
        const int c = lane + i * 32;
        float4 gm = g4[c], bt = b4[c];
        float4 r;
        r.x = (v[i].x - mu) * rs * gm.x + bt.x;
        r.y = (v[i].y - mu) * rs * gm.y + bt.y;
        r.z = (v[i].z - mu) * rs * gm.z + bt.z;
        r.w = (v[i].w - mu) * rs * gm.w + bt.w;
        o4[c] = r;
    }
}

// ---------------- launch ----------------
extern "C" void kernel_launch(void* const* d_in, const int* in_sizes, int n_in,
                              void* d_out, int out_size)
{
    (void)in_sizes; (void)n_in; (void)out_size;
    const float* x     = (const float*)d_in[0];
    const float* Wq    = (const float*)d_in[1];
    const float* bq    = (const float*)d_in[2];
    const float* Wk    = (const float*)d_in[3];
    const float* bk    = (const float*)d_in[4];
    const float* Wv    = (const float*)d_in[5];
    const float* bv    = (const float*)d_in[6];
    const float* Wo    = (const float*)d_in[7];
    const float* bo    = (const float*)d_in[8];
    const float* gamma = (const float*)d_in[9];
    const float* beta  = (const float*)d_in[10];
    float* out = (float*)d_out;

    cudaFuncSetAttribute(flash_tc_kernel,
                         cudaFuncAttributeMaxDynamicSharedMemorySize, FLASH_SMEM);
    cudaFuncSetAttribute(gemm_tc_kernel,
                         cudaFuncAttributeMaxDynamicSharedMemorySize, GEMM_SMEM);

    __nv_bfloat16* d_xh = nullptr;
    __nv_bfloat16* d_Wh = nullptr;
    cudaGetSymbolAddress((void**)&d_xh, g_xh);
    cudaGetSymbolAddress((void**)&d_Wh, g_Wh);

    // pre-pass: fp32 -> bf16
    const int nx4 = Mv * Dv / 4;
    const int nw4 = Dv * Dv / 4;
    bf16_cvt_x_kernel<<<(nx4 + 255) / 256, 256>>>(x, d_xh, nx4);
    bf16_cvt_kernel<<<dim3((nw4 + 255) / 256, 4), 256>>>(Wq, Wk, Wv, Wo, d_Wh, nw4);

    // fused QKV projection
    gemm_tc_kernel<<<dim3(24, Mv / 128), 256, GEMM_SMEM>>>(0, bq, bk, bv, nullptr, nullptr);

    // attention (Br=64 tiles, 4 CTAs/SM)
    flash_tc_kernel<<<dim3(Lv / 64, Bv * Hv), 128, FLASH_SMEM>>>();

    // output projection + residual
    gemm_tc_kernel<<<dim3(8, Mv / 128), 256, GEMM_SMEM>>>(1, nullptr, nullptr, nullptr, bo, x);

    layernorm_kernel<<<Mv / 8, 256>>>(gamma, beta, out);
}